// round 4
// baseline (speedup 1.0000x reference)
#include <cuda_runtime.h>
#include <math.h>

#define TOPK   64
#define NANCH  340
#define MS     28
#define NROI   128          // B(2) * TOPK(64)

// ---------------- device scratch (no allocation allowed) ----------------
__device__ float g_box [NROI][4];
__device__ int   g_bint[NROI][4];
__device__ int   g_keep[NROI];
__device__ float g_logit[NROI][MS*MS];
// padded roi input: 256 ch x 30x30 (zero ring for SAME conv)
__device__ float g_roi[NROI][256][900];

// out layout (fp32): scores[128] | boxes[512] | labels[128] | masks[2*64*512*512] | keep[128]
#define OFF_SCORES 0
#define OFF_BOXES  128
#define OFF_LABELS 640
#define OFF_MASKS  768
#define OFF_KEEP   33555200

// =======================================================================
// K1: decode + top-k (exact lax.top_k tie semantics) + NMS + small outputs
// =======================================================================
__global__ void k1_detect(const float* __restrict__ pred0,
                          const float* __restrict__ pred1,
                          const float* __restrict__ pred2,
                          const float* __restrict__ pred3,
                          float* __restrict__ out)
{
    int b   = blockIdx.x;
    int tid = threadIdx.x;

    __shared__ float sbox[NANCH][4];
    __shared__ unsigned long long skey[NANCH];
    __shared__ unsigned long long red[384];
    __shared__ int   topidx[TOPK];
    __shared__ float topsc [TOPK];
    __shared__ float kbox[TOPK][4];
    __shared__ int   keepf[TOPK];

    if (tid < NANCH) {
        int i = tid, li, H, stride;
        const float* pp;
        if      (i < 256) { li = i;       H = 16; stride = 32;  pp = pred0; }
        else if (i < 320) { li = i - 256; H = 8;  stride = 64;  pp = pred1; }
        else if (i < 336) { li = i - 320; H = 4;  stride = 128; pp = pred2; }
        else              { li = i - 336; H = 2;  stride = 256; pp = pred3; }
        int hw = H * H;
        const float* base = pp + b * 6 * hw;
        float v0 = base[li];
        float v1 = base[hw   + li];
        float v2 = base[2*hw + li];
        float v3 = base[3*hw + li];
        float v4 = base[4*hw + li];
        int y = li / H, x = li % H;
        float cx = (v0 + (float)x) * (float)stride;
        float cy = (v1 + (float)y) * (float)stride;
        float w  = expf(v2) * (float)stride;
        float h  = expf(v3) * (float)stride;
        sbox[i][0] = cx - w * 0.5f;
        sbox[i][1] = cy - h * 0.5f;
        sbox[i][2] = cx + w * 0.5f;
        sbox[i][3] = cy + h * 0.5f;
        float sc   = 1.f / (1.f + expf(-v4));
        float sval = (sc > 0.5f) ? sc : 0.f;        // where(valid, score, 0)
        // key: score bits (nonneg float, monotone) | inverted index (tie -> lower idx)
        skey[i] = ((unsigned long long)__float_as_uint(sval) << 32)
                | (unsigned long long)(0xFFFFFFFFu - (unsigned)i);
    }
    __syncthreads();

    // top-64 selection (exact descending order, stable ties)
    // FIX: fold 384 -> 256 first, then a clean power-of-two tree (old code
    // used s=192 start, whose 3->1 tail dropped red[2]).
    for (int k = 0; k < TOPK; k++) {
        red[tid] = (tid < NANCH) ? skey[tid] : 0ULL;
        __syncthreads();
        if (tid < 128) { if (red[tid + 256] > red[tid]) red[tid] = red[tid + 256]; }
        __syncthreads();
        for (int s = 128; s > 0; s >>= 1) {
            if (tid < s) { if (red[tid + s] > red[tid]) red[tid] = red[tid + s]; }
            __syncthreads();
        }
        if (tid == 0) {
            unsigned long long best = red[0];
            int idx   = (int)(0xFFFFFFFFu - (unsigned)(best & 0xFFFFFFFFu));
            topidx[k] = idx;
            topsc [k] = __uint_as_float((unsigned)(best >> 32));
            skey[idx] = 0ULL;
        }
        __syncthreads();
    }

    if (tid < TOPK) {
        int idx = topidx[tid];
        for (int j = 0; j < 4; j++) kbox[tid][j] = sbox[idx][j];
        keepf[tid] = (topsc[tid] > 0.5f) ? 1 : 0;
    }
    __syncthreads();

    // sequential NMS (labels all 0 -> no class offset)
    for (int i = 0; i < TOPK; i++) {
        if (tid < TOPK && tid > i && keepf[tid] && keepf[i]) {
            float ax0=kbox[i][0], ay0=kbox[i][1], ax1=kbox[i][2], ay1=kbox[i][3];
            float bx0=kbox[tid][0], by0=kbox[tid][1], bx1=kbox[tid][2], by1=kbox[tid][3];
            float aa = fmaxf(ax1-ax0,0.f)*fmaxf(ay1-ay0,0.f);
            float ab = fmaxf(bx1-bx0,0.f)*fmaxf(by1-by0,0.f);
            float ix0 = fmaxf(ax0,bx0), iy0 = fmaxf(ay0,by0);
            float ix1 = fminf(ax1,bx1), iy1 = fminf(ay1,by1);
            float inter = fmaxf(ix1-ix0,0.f)*fmaxf(iy1-iy0,0.f);
            float uni = aa + ab - inter;
            float iou = inter / fmaxf(uni, 1e-9f);
            if (iou > 0.5f) keepf[tid] = 0;
        }
        __syncthreads();
    }

    if (tid < TOPK) {
        int r  = b * TOPK + tid;
        int kp = keepf[tid];
        out[OFF_SCORES + r] = kp ? topsc[tid] : 0.f;
        for (int j = 0; j < 4; j++) out[OFF_BOXES + r*4 + j] = kbox[tid][j];
        out[OFF_LABELS + r] = 0.f;
        out[OFF_KEEP   + r] = kp ? 1.f : 0.f;
        g_keep[r] = kp;
        for (int j = 0; j < 4; j++) {
            g_box[r][j]  = kbox[tid][j];
            float c = fminf(fmaxf(kbox[tid][j], 0.f), 511.f);
            g_bint[r][j] = (int)c;
        }
    }
}

// =======================================================================
// K2: ROI-align of nearest-upsampled merged feature into padded scratch
// grid (8 ch-groups, 128 rois), 256 threads
// =======================================================================
__global__ void k2_sample(const float* __restrict__ f0,
                          const float* __restrict__ f1,
                          const float* __restrict__ f2,
                          const float* __restrict__ f3)
{
    int r = blockIdx.y;
    if (!g_keep[r]) return;
    int b = r >> 6;
    float bx0 = g_box[r][0]*0.25f, by0 = g_box[r][1]*0.25f;
    float bx1 = g_box[r][2]*0.25f, by1 = g_box[r][3]*0.25f;
    float bw = (bx1 - bx0) / 28.f;
    float bh = (by1 - by0) / 28.f;
    const float* feats[4] = {f0, f1, f2, f3};
    int cbase = blockIdx.x * 32;

    for (int e = threadIdx.x; e < 32*900; e += blockDim.x) {
        int cl = e / 900; int pe = e - cl*900;
        int py = pe / 30; int px = pe - py*30;
        int c  = cbase + cl;
        float val = 0.f;
        if (py >= 1 && py <= 28 && px >= 1 && px <= 28) {
            int gx = px - 1, gy = py - 1;
            float xx = bx0 + ((float)gx + 0.5f) * bw;
            float yy = by0 + ((float)gy + 0.5f) * bh;
            xx = fminf(fmaxf(xx, 0.f), 127.f);
            yy = fminf(fmaxf(yy, 0.f), 127.f);
            int x0 = (int)floorf(xx), y0 = (int)floorf(yy);
            int x1 = min(x0 + 1, 127), y1 = min(y0 + 1, 127);
            float fx = xx - (float)x0, fy = yy - (float)y0;
            int l = c >> 6, cc = c & 63, dim = 128 >> l;
            const float* fp = feats[l] + (size_t)(b*64 + cc) * dim * dim;
            float v00 = fp[(y0>>l)*dim + (x0>>l)];
            float v01 = fp[(y0>>l)*dim + (x1>>l)];
            float v10 = fp[(y1>>l)*dim + (x0>>l)];
            float v11 = fp[(y1>>l)*dim + (x1>>l)];
            val = v00*(1.f-fy)*(1.f-fx) + v01*(1.f-fy)*fx
                + v10*fy*(1.f-fx)       + v11*fy*fx;
        }
        g_roi[r][c][pe] = val;
    }
}

// =======================================================================
// K3: conv1(3x3,256->128)+SiLU fused with conv2(1x1,128->1) -> logits
// grid (7 row-tiles of 4 rows, 128 rois), block 256 = 16x16
// each thread: 8 out-ch x 7 px register tile
// =======================================================================
__global__ void __launch_bounds__(256) k3_conv(const float* __restrict__ w1,
                                               const float* __restrict__ b1,
                                               const float* __restrict__ w2,
                                               const float* __restrict__ b2)
{
    int r = blockIdx.y;
    if (!g_keep[r]) return;
    int rt  = blockIdx.x;           // row tile: rows rt*4 .. rt*4+3
    int tid = threadIdx.x;
    int tx = tid & 15, ty = tid >> 4;

    __shared__ float in_s[4][6][30];        // 4 in-ch, rows-1..+4, padded cols
    __shared__ float w_s [4][9][128];       // [ci][tap][oc]
    __shared__ float redbuf[16][112];

    float acc[8][7];
    #pragma unroll
    for (int o = 0; o < 8; o++)
        #pragma unroll
        for (int p = 0; p < 7; p++) acc[o][p] = 0.f;

    int pr[7], pc[7];
    #pragma unroll
    for (int p = 0; p < 7; p++) {
        int px = tx + 16 * p;               // 0..111 (4 rows x 28 cols)
        pr[p] = px / 28; pc[p] = px % 28;
    }
    int oc0 = ty * 8;

    for (int ci0 = 0; ci0 < 256; ci0 += 4) {
        for (int e = tid; e < 720; e += 256) {
            int c = e / 180; int rem = e - c*180;
            int row = rem / 30; int col = rem - row*30;
            in_s[c][row][col] = g_roi[r][ci0 + c][(rt*4 + row)*30 + col];
        }
        for (int e = tid; e < 4608; e += 256) {
            int c = e / 1152; int rem = e - c*1152;
            int tap = rem >> 7; int oc = rem & 127;
            w_s[c][tap][oc] = w1[(size_t)oc*2304 + (ci0 + c)*9 + tap];
        }
        __syncthreads();
        #pragma unroll
        for (int c = 0; c < 4; c++) {
            #pragma unroll
            for (int ky = 0; ky < 3; ky++) {
                #pragma unroll
                for (int kx = 0; kx < 3; kx++) {
                    float a[8];
                    #pragma unroll
                    for (int o = 0; o < 8; o++) a[o] = w_s[c][ky*3+kx][oc0+o];
                    #pragma unroll
                    for (int p = 0; p < 7; p++) {
                        float bv = in_s[c][pr[p]+ky][pc[p]+kx];
                        #pragma unroll
                        for (int o = 0; o < 8; o++) acc[o][p] += a[o] * bv;
                    }
                }
            }
        }
        __syncthreads();
    }

    // SiLU + 1x1 conv partials
    float lp[7];
    #pragma unroll
    for (int p = 0; p < 7; p++) lp[p] = 0.f;
    #pragma unroll
    for (int o = 0; o < 8; o++) {
        int oc = oc0 + o;
        float bias = b1[oc];
        float wv   = w2[oc];
        #pragma unroll
        for (int p = 0; p < 7; p++) {
            float h  = acc[o][p] + bias;
            float sg = 1.f / (1.f + expf(-h));
            lp[p] += wv * (h * sg);
        }
    }
    #pragma unroll
    for (int p = 0; p < 7; p++) redbuf[ty][tx + 16*p] = lp[p];
    __syncthreads();
    if (tid < 112) {
        float s = b2[0];
        #pragma unroll
        for (int t = 0; t < 16; t++) s += redbuf[t][tid];
        int row = rt*4 + tid / 28, col = tid % 28;
        g_logit[r][row*28 + col] = s;   // sign(logit) == (sigmoid > 0.5)
    }
}

// =======================================================================
// K4: paste -> binary masks (float 0/1). grid (512 rows, 128 rois), 256 thr
// =======================================================================
__global__ void k4_paste(float* __restrict__ out)
{
    int r = blockIdx.y;
    int y = blockIdx.x;
    int tid = threadIdx.x;
    float2* dst = (float2*)(out + OFF_MASKS + (size_t)r*262144 + (size_t)y*512);

    __shared__ float brow[28];
    float2 v = make_float2(0.f, 0.f);
    int kp = g_keep[r];
    if (kp) {
        int x0 = g_bint[r][0], y0 = g_bint[r][1];
        int x1 = g_bint[r][2], y1 = g_bint[r][3];
        if (y >= y0 && y <= y1) {
            int h = y1 - y0 + 1, w = x1 - x0 + 1;
            int iy = min((y - y0) * 28 / h, 27);
            if (tid < 28) brow[tid] = (g_logit[r][iy*28 + tid] > 0.f) ? 1.f : 0.f;
            __syncthreads();
            int xa = tid * 2;
            if (xa >= x0 && xa <= x1) {
                int ix = min((xa - x0) * 28 / w, 27);
                v.x = brow[ix];
            }
            int xb = xa + 1;
            if (xb >= x0 && xb <= x1) {
                int ix = min((xb - x0) * 28 / w, 27);
                v.y = brow[ix];
            }
        }
    }
    dst[tid] = v;
}

// =======================================================================
extern "C" void kernel_launch(void* const* d_in, const int* in_sizes, int n_in,
                              void* d_out, int out_size)
{
    const float* pred0 = (const float*)d_in[0];
    const float* pred1 = (const float*)d_in[1];
    const float* pred2 = (const float*)d_in[2];
    const float* pred3 = (const float*)d_in[3];
    const float* feat0 = (const float*)d_in[4];
    const float* feat1 = (const float*)d_in[5];
    const float* feat2 = (const float*)d_in[6];
    const float* feat3 = (const float*)d_in[7];
    const float* w1    = (const float*)d_in[8];
    const float* b1    = (const float*)d_in[9];
    const float* w2    = (const float*)d_in[10];
    const float* b2    = (const float*)d_in[11];
    float* out = (float*)d_out;
    (void)in_sizes; (void)n_in; (void)out_size;

    k1_detect<<<2, 384>>>(pred0, pred1, pred2, pred3, out);
    k2_sample<<<dim3(8, NROI), 256>>>(feat0, feat1, feat2, feat3);
    k3_conv  <<<dim3(7, NROI), 256>>>(w1, b1, w2, b2);
    k4_paste <<<dim3(512, NROI), 256>>>(out);
}

// round 5
// speedup vs baseline: 1.1214x; 1.1214x over previous
#include <cuda_runtime.h>
#include <math.h>

#define TOPK   64
#define NANCH  340
#define MS     28
#define NROI   128          // B(2) * TOPK(64)

typedef unsigned long long ull;

// ---------------- device scratch (no allocation allowed) ----------------
__device__ float g_box [NROI][4];
__device__ int   g_bint[NROI][4];
__device__ int   g_keep[NROI];
__device__ float g_logit[NROI][MS*MS];
// padded roi input: 256 ch x 30x30 (zero ring for SAME conv)
__device__ float g_roi[NROI][256][900];

// out layout (fp32): scores[128] | boxes[512] | labels[128] | masks[2*64*512*512] | keep[128]
#define OFF_SCORES 0
#define OFF_BOXES  128
#define OFF_LABELS 640
#define OFF_MASKS  768
#define OFF_KEEP   33555200

// ---------------- packed fp32x2 helpers (Blackwell FFMA2) ----------------
__device__ __forceinline__ ull pack2(float x) {
    ull r;
    asm("mov.b64 %0, {%1, %1};" : "=l"(r) : "f"(x));
    return r;
}
__device__ __forceinline__ void fma2(ull& d, ull a, ull b) {
    asm("fma.rn.f32x2 %0, %1, %2, %0;" : "+l"(d) : "l"(a), "l"(b));
}
__device__ __forceinline__ float2 unpack2(ull v) {
    float2 f;
    asm("mov.b64 {%0, %1}, %2;" : "=f"(f.x), "=f"(f.y) : "l"(v));
    return f;
}

// =======================================================================
// K1: decode + top-k (exact lax.top_k tie semantics) + NMS + small outputs
// =======================================================================
__global__ void k1_detect(const float* __restrict__ pred0,
                          const float* __restrict__ pred1,
                          const float* __restrict__ pred2,
                          const float* __restrict__ pred3,
                          float* __restrict__ out)
{
    int b   = blockIdx.x;
    int tid = threadIdx.x;

    __shared__ float sbox[NANCH][4];
    __shared__ ull skey[NANCH];
    __shared__ ull red[384];
    __shared__ int   topidx[TOPK];
    __shared__ float topsc [TOPK];
    __shared__ float kbox[TOPK][4];
    __shared__ int   keepf[TOPK];

    if (tid < NANCH) {
        int i = tid, li, H, stride;
        const float* pp;
        if      (i < 256) { li = i;       H = 16; stride = 32;  pp = pred0; }
        else if (i < 320) { li = i - 256; H = 8;  stride = 64;  pp = pred1; }
        else if (i < 336) { li = i - 320; H = 4;  stride = 128; pp = pred2; }
        else              { li = i - 336; H = 2;  stride = 256; pp = pred3; }
        int hw = H * H;
        const float* base = pp + b * 6 * hw;
        float v0 = base[li];
        float v1 = base[hw   + li];
        float v2 = base[2*hw + li];
        float v3 = base[3*hw + li];
        float v4 = base[4*hw + li];
        int y = li / H, x = li % H;
        float cx = (v0 + (float)x) * (float)stride;
        float cy = (v1 + (float)y) * (float)stride;
        float w  = expf(v2) * (float)stride;
        float h  = expf(v3) * (float)stride;
        sbox[i][0] = cx - w * 0.5f;
        sbox[i][1] = cy - h * 0.5f;
        sbox[i][2] = cx + w * 0.5f;
        sbox[i][3] = cy + h * 0.5f;
        float sc   = 1.f / (1.f + expf(-v4));
        float sval = (sc > 0.5f) ? sc : 0.f;        // where(valid, score, 0)
        // key: score bits (nonneg float, monotone) | inverted index (tie -> lower idx)
        skey[i] = ((ull)__float_as_uint(sval) << 32)
                | (ull)(0xFFFFFFFFu - (unsigned)i);
    }
    __syncthreads();

    // top-64 selection (exact descending order, stable ties)
    for (int k = 0; k < TOPK; k++) {
        red[tid] = (tid < NANCH) ? skey[tid] : 0ULL;
        __syncthreads();
        if (tid < 128) { if (red[tid + 256] > red[tid]) red[tid] = red[tid + 256]; }
        __syncthreads();
        for (int s = 128; s > 0; s >>= 1) {
            if (tid < s) { if (red[tid + s] > red[tid]) red[tid] = red[tid + s]; }
            __syncthreads();
        }
        if (tid == 0) {
            ull best = red[0];
            int idx   = (int)(0xFFFFFFFFu - (unsigned)(best & 0xFFFFFFFFu));
            topidx[k] = idx;
            topsc [k] = __uint_as_float((unsigned)(best >> 32));
            skey[idx] = 0ULL;
        }
        __syncthreads();
    }

    if (tid < TOPK) {
        int idx = topidx[tid];
        for (int j = 0; j < 4; j++) kbox[tid][j] = sbox[idx][j];
        keepf[tid] = (topsc[tid] > 0.5f) ? 1 : 0;
    }
    __syncthreads();

    // sequential NMS (labels all 0 -> no class offset)
    for (int i = 0; i < TOPK; i++) {
        if (tid < TOPK && tid > i && keepf[tid] && keepf[i]) {
            float ax0=kbox[i][0], ay0=kbox[i][1], ax1=kbox[i][2], ay1=kbox[i][3];
            float bx0=kbox[tid][0], by0=kbox[tid][1], bx1=kbox[tid][2], by1=kbox[tid][3];
            float aa = fmaxf(ax1-ax0,0.f)*fmaxf(ay1-ay0,0.f);
            float ab = fmaxf(bx1-bx0,0.f)*fmaxf(by1-by0,0.f);
            float ix0 = fmaxf(ax0,bx0), iy0 = fmaxf(ay0,by0);
            float ix1 = fminf(ax1,bx1), iy1 = fminf(ay1,by1);
            float inter = fmaxf(ix1-ix0,0.f)*fmaxf(iy1-iy0,0.f);
            float uni = aa + ab - inter;
            float iou = inter / fmaxf(uni, 1e-9f);
            if (iou > 0.5f) keepf[tid] = 0;
        }
        __syncthreads();
    }

    if (tid < TOPK) {
        int r  = b * TOPK + tid;
        int kp = keepf[tid];
        out[OFF_SCORES + r] = kp ? topsc[tid] : 0.f;
        for (int j = 0; j < 4; j++) out[OFF_BOXES + r*4 + j] = kbox[tid][j];
        out[OFF_LABELS + r] = 0.f;
        out[OFF_KEEP   + r] = kp ? 1.f : 0.f;
        g_keep[r] = kp;
        for (int j = 0; j < 4; j++) {
            g_box[r][j]  = kbox[tid][j];
            float c = fminf(fmaxf(kbox[tid][j], 0.f), 511.f);
            g_bint[r][j] = (int)c;
        }
    }
}

// =======================================================================
// K2: ROI-align of nearest-upsampled merged feature into padded scratch
// =======================================================================
__global__ void k2_sample(const float* __restrict__ f0,
                          const float* __restrict__ f1,
                          const float* __restrict__ f2,
                          const float* __restrict__ f3)
{
    int r = blockIdx.y;
    if (!g_keep[r]) return;
    int b = r >> 6;
    float bx0 = g_box[r][0]*0.25f, by0 = g_box[r][1]*0.25f;
    float bx1 = g_box[r][2]*0.25f, by1 = g_box[r][3]*0.25f;
    float bw = (bx1 - bx0) / 28.f;
    float bh = (by1 - by0) / 28.f;
    const float* feats[4] = {f0, f1, f2, f3};
    int cbase = blockIdx.x * 32;

    for (int e = threadIdx.x; e < 32*900; e += blockDim.x) {
        int cl = e / 900; int pe = e - cl*900;
        int py = pe / 30; int px = pe - py*30;
        int c  = cbase + cl;
        float val = 0.f;
        if (py >= 1 && py <= 28 && px >= 1 && px <= 28) {
            int gx = px - 1, gy = py - 1;
            float xx = bx0 + ((float)gx + 0.5f) * bw;
            float yy = by0 + ((float)gy + 0.5f) * bh;
            xx = fminf(fmaxf(xx, 0.f), 127.f);
            yy = fminf(fmaxf(yy, 0.f), 127.f);
            int x0 = (int)floorf(xx), y0 = (int)floorf(yy);
            int x1 = min(x0 + 1, 127), y1 = min(y0 + 1, 127);
            float fx = xx - (float)x0, fy = yy - (float)y0;
            int l = c >> 6, cc = c & 63, dim = 128 >> l;
            const float* fp = feats[l] + (size_t)(b*64 + cc) * dim * dim;
            float v00 = fp[(y0>>l)*dim + (x0>>l)];
            float v01 = fp[(y0>>l)*dim + (x1>>l)];
            float v10 = fp[(y1>>l)*dim + (x0>>l)];
            float v11 = fp[(y1>>l)*dim + (x1>>l)];
            val = v00*(1.f-fy)*(1.f-fx) + v01*(1.f-fy)*fx
                + v10*fy*(1.f-fx)       + v11*fy*fx;
        }
        g_roi[r][c][pe] = val;
    }
}

// =======================================================================
// K3: conv1(3x3,256->128)+SiLU fused with conv2(1x1,128->1) -> logits
// Packed fp32x2 over output-channel PAIRS: each thread owns 4 oc-pairs x 7 px.
// Weight pairs are contiguous in w_s -> single LDS.64; pixel is broadcast-
// packed once and reused by 4 FFMA2. Accumulation order per (oc,px) is
// identical to the scalar version (c -> ky -> kx), so results are bit-equal.
// =======================================================================
__global__ void __launch_bounds__(256) k3_conv(const float* __restrict__ w1,
                                               const float* __restrict__ b1,
                                               const float* __restrict__ w2,
                                               const float* __restrict__ b2)
{
    int r = blockIdx.y;
    if (!g_keep[r]) return;
    int rt  = blockIdx.x;           // row tile: rows rt*4 .. rt*4+3
    int tid = threadIdx.x;
    int tx = tid & 15, ty = tid >> 4;

    __shared__ float in_s[4][6][30];                    // 4 in-ch, rows-1..+4
    __shared__ __align__(16) float w_s[4][9][128];      // [ci][tap][oc]
    __shared__ float redbuf[16][112];

    ull acc[4][7];
    ull z = pack2(0.f);
    #pragma unroll
    for (int j = 0; j < 4; j++)
        #pragma unroll
        for (int p = 0; p < 7; p++) acc[j][p] = z;

    int pr[7], pc[7];
    #pragma unroll
    for (int p = 0; p < 7; p++) {
        int px = tx + 16 * p;               // 0..111 (4 rows x 28 cols)
        pr[p] = px / 28; pc[p] = px % 28;
    }
    int oc0 = ty * 8;

    for (int ci0 = 0; ci0 < 256; ci0 += 4) {
        for (int e = tid; e < 720; e += 256) {
            int c = e / 180; int rem = e - c*180;
            int row = rem / 30; int col = rem - row*30;
            in_s[c][row][col] = g_roi[r][ci0 + c][(rt*4 + row)*30 + col];
        }
        for (int e = tid; e < 4608; e += 256) {
            int c = e / 1152; int rem = e - c*1152;
            int tap = rem >> 7; int oc = rem & 127;
            w_s[c][tap][oc] = w1[(size_t)oc*2304 + (ci0 + c)*9 + tap];
        }
        __syncthreads();
        #pragma unroll
        for (int c = 0; c < 4; c++) {
            #pragma unroll
            for (int ky = 0; ky < 3; ky++) {
                #pragma unroll
                for (int kx = 0; kx < 3; kx++) {
                    const ull* wp = (const ull*)&w_s[c][ky*3+kx][oc0];
                    ull w0 = wp[0], w1p = wp[1], w2p = wp[2], w3p = wp[3];
                    #pragma unroll
                    for (int p = 0; p < 7; p++) {
                        ull bb = pack2(in_s[c][pr[p]+ky][pc[p]+kx]);
                        fma2(acc[0][p], w0,  bb);
                        fma2(acc[1][p], w1p, bb);
                        fma2(acc[2][p], w2p, bb);
                        fma2(acc[3][p], w3p, bb);
                    }
                }
            }
        }
        __syncthreads();
    }

    // SiLU + 1x1 conv partials
    float lp[7];
    #pragma unroll
    for (int p = 0; p < 7; p++) lp[p] = 0.f;
    #pragma unroll
    for (int j = 0; j < 4; j++) {
        int oca = oc0 + 2*j, ocb = oc0 + 2*j + 1;
        float ba = b1[oca], bb_ = b1[ocb];
        float wa = w2[oca], wb = w2[ocb];
        #pragma unroll
        for (int p = 0; p < 7; p++) {
            float2 v = unpack2(acc[j][p]);
            float ha = v.x + ba;
            float hb = v.y + bb_;
            lp[p] += wa * (ha / (1.f + expf(-ha)));
            lp[p] += wb * (hb / (1.f + expf(-hb)));
        }
    }
    #pragma unroll
    for (int p = 0; p < 7; p++) redbuf[ty][tx + 16*p] = lp[p];
    __syncthreads();
    if (tid < 112) {
        float s = b2[0];
        #pragma unroll
        for (int t = 0; t < 16; t++) s += redbuf[t][tid];
        int row = rt*4 + tid / 28, col = tid % 28;
        g_logit[r][row*28 + col] = s;   // sign(logit) == (sigmoid > 0.5)
    }
}

// =======================================================================
// K4: paste -> binary masks (float 0/1). grid (512 rows, 128 rois), 128 thr
// float4 stores
// =======================================================================
__global__ void k4_paste(float* __restrict__ out)
{
    int r = blockIdx.y;
    int y = blockIdx.x;
    int tid = threadIdx.x;
    float4* dst = (float4*)(out + OFF_MASKS + (size_t)r*262144 + (size_t)y*512);

    __shared__ float brow[28];
    float4 v = make_float4(0.f, 0.f, 0.f, 0.f);
    int kp = g_keep[r];
    if (kp) {
        int x0 = g_bint[r][0], y0 = g_bint[r][1];
        int x1 = g_bint[r][2], y1 = g_bint[r][3];
        if (y >= y0 && y <= y1) {
            int h = y1 - y0 + 1, w = x1 - x0 + 1;
            int iy = min((y - y0) * 28 / h, 27);
            if (tid < 28) brow[tid] = (g_logit[r][iy*28 + tid] > 0.f) ? 1.f : 0.f;
            __syncthreads();
            float* vv = (float*)&v;
            #pragma unroll
            for (int q = 0; q < 4; q++) {
                int x = tid * 4 + q;
                if (x >= x0 && x <= x1) {
                    int ix = min((x - x0) * 28 / w, 27);
                    vv[q] = brow[ix];
                }
            }
        }
    }
    dst[tid] = v;
}

// =======================================================================
extern "C" void kernel_launch(void* const* d_in, const int* in_sizes, int n_in,
                              void* d_out, int out_size)
{
    const float* pred0 = (const float*)d_in[0];
    const float* pred1 = (const float*)d_in[1];
    const float* pred2 = (const float*)d_in[2];
    const float* pred3 = (const float*)d_in[3];
    const float* feat0 = (const float*)d_in[4];
    const float* feat1 = (const float*)d_in[5];
    const float* feat2 = (const float*)d_in[6];
    const float* feat3 = (const float*)d_in[7];
    const float* w1    = (const float*)d_in[8];
    const float* b1    = (const float*)d_in[9];
    const float* w2    = (const float*)d_in[10];
    const float* b2    = (const float*)d_in[11];
    float* out = (float*)d_out;
    (void)in_sizes; (void)n_in; (void)out_size;

    k1_detect<<<2, 384>>>(pred0, pred1, pred2, pred3, out);
    k2_sample<<<dim3(8, NROI), 256>>>(feat0, feat1, feat2, feat3);
    k3_conv  <<<dim3(7, NROI), 256>>>(w1, b1, w2, b2);
    k4_paste <<<dim3(512, NROI), 128>>>(out);
}